// round 14
// baseline (speedup 1.0000x reference)
#include <cuda_runtime.h>
#include <cuda_bf16.h>
#include <math.h>
#include <stdint.h>

#define BB   4
#define NTOK 4096
#define CC   256
#define DD   32
#define MM   (BB * NTOK)   // 16384

// Scratch (allocation-free per harness rules)
__device__ __nv_bfloat16 g_xb[MM * CC];
__device__ __nv_bfloat16 g_q[MM * DD];
__device__ __nv_bfloat16 g_k[MM * DD];
__device__ __nv_bfloat16 g_v[MM * CC];
__device__ __nv_bfloat16 g_att[MM * CC];
__device__ __nv_bfloat16 g_wqkb[CC * 64];   // cols 0-31 wq*qscale, 32-63 wk
__device__ __nv_bfloat16 g_wvb[CC * CC];
__device__ __nv_bfloat16 g_wob[CC * CC];
__device__ float         g_bqk[64];

// ---------------------------------------------------------------------------
// PTX helpers
// ---------------------------------------------------------------------------
__device__ __forceinline__ uint32_t smem_u32(const void* p) {
    return (uint32_t)__cvta_generic_to_shared(p);
}
__device__ __forceinline__ void ldsm_x4(uint32_t& r0, uint32_t& r1, uint32_t& r2, uint32_t& r3, uint32_t addr) {
    asm volatile("ldmatrix.sync.aligned.m8n8.x4.shared.b16 {%0,%1,%2,%3}, [%4];\n"
                 : "=r"(r0), "=r"(r1), "=r"(r2), "=r"(r3) : "r"(addr));
}
__device__ __forceinline__ void ldsm_x4_trans(uint32_t& r0, uint32_t& r1, uint32_t& r2, uint32_t& r3, uint32_t addr) {
    asm volatile("ldmatrix.sync.aligned.m8n8.x4.trans.shared.b16 {%0,%1,%2,%3}, [%4];\n"
                 : "=r"(r0), "=r"(r1), "=r"(r2), "=r"(r3) : "r"(addr));
}
__device__ __forceinline__ void mma_bf16(float* c, uint32_t a0, uint32_t a1, uint32_t a2, uint32_t a3,
                                         uint32_t b0, uint32_t b1) {
    asm volatile(
        "mma.sync.aligned.m16n8k16.row.col.f32.bf16.bf16.f32 "
        "{%0,%1,%2,%3}, {%4,%5,%6,%7}, {%8,%9}, {%0,%1,%2,%3};\n"
        : "+f"(c[0]), "+f"(c[1]), "+f"(c[2]), "+f"(c[3])
        : "r"(a0), "r"(a1), "r"(a2), "r"(a3), "r"(b0), "r"(b1));
}
__device__ __forceinline__ void cp_async16(uint32_t smem_dst, const void* gsrc) {
    asm volatile("cp.async.cg.shared.global [%0], [%1], 16;\n" :: "r"(smem_dst), "l"(gsrc));
}
__device__ __forceinline__ void cp_async_commit() { asm volatile("cp.async.commit_group;\n"); }
__device__ __forceinline__ void cp_async_wait0()  { asm volatile("cp.async.wait_group 0;\n"); }
__device__ __forceinline__ void cp_async_wait1()  { asm volatile("cp.async.wait_group 1;\n"); }
__device__ __forceinline__ void cp_async_wait2()  { asm volatile("cp.async.wait_group 2;\n"); }

__device__ __forceinline__ uint32_t pack_bf16(float lo, float hi) {
    uint32_t r;
    asm("cvt.rn.bf16x2.f32 %0, %1, %2;" : "=r"(r) : "f"(hi), "f"(lo));
    return r;
}
__device__ __forceinline__ float ex2_fast(float x) {
    float y;
    asm("ex2.approx.ftz.f32 %0, %1;" : "=f"(y) : "f"(x));
    return y;
}

// ---------------------------------------------------------------------------
// merged fp32 -> bf16 conversion (x + all weights)
// ---------------------------------------------------------------------------
__global__ __launch_bounds__(256) void convert_all_kernel(
    const float4* __restrict__ x,
    const float* __restrict__ wq, const float* __restrict__ bq,
    const float* __restrict__ wk, const float* __restrict__ bk,
    const float* __restrict__ wv, const float* __restrict__ wo, float qscale)
{
    int i = blockIdx.x * 256 + threadIdx.x;
    float4 v = x[i];
    ((uint2*)g_xb)[i] = make_uint2(pack_bf16(v.x, v.y), pack_bf16(v.z, v.w));

    if (i < CC * CC) {
        g_wvb[i] = __float2bfloat16(wv[i]);
        g_wob[i] = __float2bfloat16(wo[i]);
    }
    if (i < CC * 64) {
        int r = i >> 6, c = i & 63;
        g_wqkb[i] = (c < 32) ? __float2bfloat16(wq[r * DD + c] * qscale)
                             : __float2bfloat16(wk[r * DD + c - 32]);
    }
    if (i < 64) g_bqk[i] = (i < 32) ? bq[i] * qscale : bk[i - 32];
}

// ---------------------------------------------------------------------------
// bf16 tensor-core GEMM, 4-stage cp.async pipeline (dynamic smem).
// MODE: 0 = bf16 out, 1 = fp32 out + resid, 2 = split Q/K bf16 out.
// ---------------------------------------------------------------------------
#define GXS 40   // A tile row stride (bf16)
#define GEMM_A_STAGE (128 * GXS * 2)   // 10240 B

template <int CTA_N, int MODE>
__global__ __launch_bounds__(256, 2) void tc_gemm_kernel(
    const __nv_bfloat16* __restrict__ A, const __nv_bfloat16* __restrict__ W,
    const float* __restrict__ bias, const float* __restrict__ resid,
    void* __restrict__ Yv, void* __restrict__ Y2, int N)
{
    constexpr int WS = CTA_N + 8;
    constexpr int NW = CTA_N / 8;
    constexpr int MW = 2;
    constexpr int NB = (CTA_N == 128) ? 8 : 4;
    constexpr int W_STAGE = 32 * WS * 2;

    extern __shared__ char gsm[];
    const uint32_t base = smem_u32(gsm);

    const int tid  = threadIdx.x;
    const int lane = tid & 31;
    const int warp = tid >> 5;
    const int wm   = warp >> 1;
    const int wn   = warp & 1;
    const int row0 = blockIdx.y * 128;
    const int n0   = blockIdx.x * CTA_N;

    auto sA_u = [&](int s) { return base + s * GEMM_A_STAGE; };
    auto sW_u = [&](int s) { return base + 4 * GEMM_A_STAGE + s * W_STAGE; };

    auto load_chunk = [&](int buf, int k0) {
        #pragma unroll
        for (int i = 0; i < 2; i++) {
            int idx = tid + i * 256;
            int r = idx >> 2, c = idx & 3;
            cp_async16(sA_u(buf) + r * (GXS * 2) + c * 16,
                       A + (size_t)(row0 + r) * CC + k0 + c * 8);
        }
        #pragma unroll
        for (int i = 0; i < (32 * NW + 255) / 256; i++) {
            int idx = tid + i * 256;
            int r = idx / NW, c = idx % NW;
            cp_async16(sW_u(buf) + r * (WS * 2) + c * 16,
                       W + (size_t)(k0 + r) * N + n0 + c * 8);
        }
        cp_async_commit();
    };

    load_chunk(0, 0);
    load_chunk(1, 32);
    load_chunk(2, 64);

    float acc[MW][NB][4];
    #pragma unroll
    for (int m = 0; m < MW; m++)
        #pragma unroll
        for (int nb = 0; nb < NB; nb++)
            #pragma unroll
            for (int q = 0; q < 4; q++) acc[m][nb][q] = 0.0f;

    const int arow = (lane & 15);
    const int acolb = ((lane >> 4) & 1) * 16;
    const int brow = (lane & 7) + ((lane >> 3) & 1) * 8;
    const int bcolb = ((lane >> 4) & 1) * 16;

    for (int ch = 0; ch < 8; ch++) {
        cp_async_wait2();
        __syncthreads();
        if (ch + 3 < 8) load_chunk((ch + 3) & 3, (ch + 3) * 32);
        else cp_async_commit();

        const uint32_t sAb = sA_u(ch & 3);
        const uint32_t sWb = sW_u(ch & 3);

        #pragma unroll
        for (int kk = 0; kk < 2; kk++) {
            uint32_t a[MW][4];
            #pragma unroll
            for (int m = 0; m < MW; m++)
                ldsm_x4(a[m][0], a[m][1], a[m][2], a[m][3],
                        sAb + (wm * (MW * 16) + m * 16 + arow) * (GXS * 2) + kk * 32 + acolb);
            #pragma unroll
            for (int nb2 = 0; nb2 < NB / 2; nb2++) {
                uint32_t b0, b1, b2, b3;
                ldsm_x4_trans(b0, b1, b2, b3,
                              sWb + (kk * 16 + brow) * (WS * 2) + (wn * (NB * 8) + nb2 * 16) * 2 + bcolb);
                #pragma unroll
                for (int m = 0; m < MW; m++) {
                    mma_bf16(acc[m][2 * nb2],     a[m][0], a[m][1], a[m][2], a[m][3], b0, b1);
                    mma_bf16(acc[m][2 * nb2 + 1], a[m][0], a[m][1], a[m][2], a[m][3], b2, b3);
                }
            }
        }
    }

    #pragma unroll
    for (int m = 0; m < MW; m++) {
        int r0 = row0 + wm * (MW * 16) + m * 16 + (lane >> 2);
        #pragma unroll
        for (int nb = 0; nb < NB; nb++) {
            int col = n0 + wn * (NB * 8) + nb * 8 + (lane & 3) * 2;
            #pragma unroll
            for (int h = 0; h < 2; h++) {
                int r = r0 + h * 8;
                float c0 = acc[m][nb][2 * h]     + bias[col];
                float c1 = acc[m][nb][2 * h + 1] + bias[col + 1];
                if (MODE == 1) {
                    float2 rr = *(const float2*)&resid[(size_t)r * N + col];
                    *(float2*)&((float*)Yv)[(size_t)r * N + col] = make_float2(c0 + rr.x, c1 + rr.y);
                } else if (MODE == 0) {
                    *(uint32_t*)&((__nv_bfloat16*)Yv)[(size_t)r * N + col] = pack_bf16(c0, c1);
                } else {
                    if (col < 32)
                        *(uint32_t*)&((__nv_bfloat16*)Yv)[(size_t)r * DD + col] = pack_bf16(c0, c1);
                    else
                        *(uint32_t*)&((__nv_bfloat16*)Y2)[(size_t)r * DD + col - 32] = pack_bf16(c0, c1);
                }
            }
        }
    }
}

// ---------------------------------------------------------------------------
// Flash attention: 64-query CTA, 8 warps = 2 wm x 4 wn, 2 CTAs/SM.
// Warp tile: 32 rows x 64 V-cols; S keys split 4-way (16 keys/warp).
// Cross-CTA overlap hides the softmax window. 2-buffered K/V/P.
// Row sums via ones-MMA.
// ---------------------------------------------------------------------------
#define KSTRIDE 40    // 80 B
#define VSTRIDE 264   // 528 B
#define A_KB    (64 * KSTRIDE * 2)    // 5120
#define A_VB    (64 * VSTRIDE * 2)    // 33792
#define PSTRIDE 72                    // 144 B
#define PBUF    (64 * PSTRIDE * 2)    // 9216
#define AT_SQ   0
#define AT_SK   (64 * KSTRIDE * 2)                 // 5120
#define AT_SV   (AT_SK + 2 * A_KB)                 // 15360
#define AT_SP   (AT_SV + 2 * A_VB)                 // 82944
#define AT_TOT  (AT_SP + 2 * PBUF)                 // 101376
#define ONE2BF  0x3F803F80u

__global__ __launch_bounds__(256, 2) void attn_kernel(
    const __nv_bfloat16* __restrict__ gq, const __nv_bfloat16* __restrict__ gk,
    const __nv_bfloat16* __restrict__ gv, __nv_bfloat16* __restrict__ gatt)
{
    extern __shared__ char sm[];
    const uint32_t smb = smem_u32(sm);

    const int tid  = threadIdx.x;
    const int lane = tid & 31;
    const int warp = tid >> 5;
    const int wm   = warp >> 2;        // 0..1 -> rows 32*wm
    const int wn   = warp & 3;         // 0..3 -> 16-key slice for S; 64-col slice for PV

    const int b  = blockIdx.y;
    const int qt = blockIdx.x;

    const __nv_bfloat16* qb = gq + ((size_t)b * NTOK + qt * 64) * DD;
    const __nv_bfloat16* kb = gk + (size_t)b * NTOK * DD;
    const __nv_bfloat16* vb = gv + (size_t)b * NTOK * CC;

    auto sK_u = [&](int s) { return smb + AT_SK + s * A_KB; };
    auto sV_u = [&](int s) { return smb + AT_SV + s * A_VB; };
    auto sP_u = [&](int p) { return smb + AT_SP + p * PBUF; };

    auto load_tile = [&](int t, int s) {
        {
            int r = tid >> 2, c = tid & 3;
            cp_async16(sK_u(s) + r * (KSTRIDE * 2) + c * 16,
                       kb + ((size_t)t * 64 + r) * DD + c * 8);
        }
        #pragma unroll
        for (int i = 0; i < 8; i++) {
            int idx = tid + i * 256;
            int vr = idx >> 5, vc = idx & 31;
            cp_async16(sV_u(s) + vr * (VSTRIDE * 2) + vc * 16,
                       vb + ((size_t)t * 64 + vr) * CC + vc * 8);
        }
        cp_async_commit();
    };

    // stage Q (64x32 bf16): one 16B chunk per thread
    {
        int r = tid >> 2, c = tid & 3;
        *(uint4*)(sm + AT_SQ + r * (KSTRIDE * 2) + c * 16) =
            *(const uint4*)(qb + (size_t)r * DD + c * 8);
    }
    load_tile(0, 0);
    __syncthreads();

    // Q fragments: [m-block][kbk][4] for rows 32*wm + 16*m
    uint32_t qA[2][2][4];
    #pragma unroll
    for (int m = 0; m < 2; m++) {
        uint32_t base = smb + AT_SQ + (32 * wm + 16 * m + (lane & 15)) * (KSTRIDE * 2)
                        + ((lane >> 4) & 1) * 16;
        ldsm_x4(qA[m][0][0], qA[m][0][1], qA[m][0][2], qA[m][0][3], base);
        ldsm_x4(qA[m][1][0], qA[m][1][1], qA[m][1][2], qA[m][1][3], base + 32);
    }

    float acc[2][8][4];
    #pragma unroll
    for (int m = 0; m < 2; m++)
        #pragma unroll
        for (int j = 0; j < 8; j++)
            #pragma unroll
            for (int q4 = 0; q4 < 4; q4++) acc[m][j][q4] = 0.0f;
    float acc1[2][4];
    #pragma unroll
    for (int m = 0; m < 2; m++)
        #pragma unroll
        for (int q4 = 0; q4 < 4; q4++) acc1[m][q4] = 0.0f;

    const int krow4  = ((lane >> 4) & 1) * 8 + (lane & 7);
    const int kcolb4 = ((lane >> 3) & 1) * 16;
    const int vrow4  = (lane & 7) + ((lane >> 3) & 1) * 8;
    const int vcolb4 = ((lane >> 4) & 1) * 16;
    const uint32_t pwr_base = (32 * wm + (lane >> 2)) * (PSTRIDE * 2) + (wn * 16 + (lane & 3) * 2) * 2;
    const uint32_t prd_base = (32 * wm + (lane & 15)) * (PSTRIDE * 2) + ((lane >> 4) & 1) * 16;

    for (int kt = 0; kt < 64; kt++) {
        __syncthreads();                       // all warps done with kt-1; V[(kt+1)&1] free
        if (kt + 1 < 64) {
            load_tile(kt + 1, (kt + 1) & 1);
            cp_async_wait1();                  // tile kt resident
        } else {
            cp_async_wait0();
        }

        // ---- S = Q @ K^T for this warp's 16-key slice, both m-blocks ----
        const uint32_t sKb = sK_u(kt & 1);
        float sfrag[2][2][4];
        #pragma unroll
        for (int m = 0; m < 2; m++)
            #pragma unroll
            for (int j = 0; j < 2; j++)
                #pragma unroll
                for (int q4 = 0; q4 < 4; q4++) sfrag[m][j][q4] = 0.0f;
        #pragma unroll
        for (int kbk = 0; kbk < 2; kbk++) {
            uint32_t b0, b1, b2, b3;
            ldsm_x4(b0, b1, b2, b3,
                    sKb + (wn * 16 + krow4) * (KSTRIDE * 2) + kbk * 32 + kcolb4);
            #pragma unroll
            for (int m = 0; m < 2; m++) {
                mma_bf16(sfrag[m][0], qA[m][kbk][0], qA[m][kbk][1], qA[m][kbk][2], qA[m][kbk][3], b0, b1);
                mma_bf16(sfrag[m][1], qA[m][kbk][0], qA[m][kbk][1], qA[m][kbk][2], qA[m][kbk][3], b2, b3);
            }
        }

        // ---- P = exp2(S) -> smem P[kt&1] (16 exps/warp) ----
        const uint32_t sPcur = sP_u(kt & 1);
        #pragma unroll
        for (int m = 0; m < 2; m++) {
            #pragma unroll
            for (int j = 0; j < 2; j++) {
                uint32_t pb_lo = pack_bf16(ex2_fast(sfrag[m][j][0]), ex2_fast(sfrag[m][j][1]));
                uint32_t pb_hi = pack_bf16(ex2_fast(sfrag[m][j][2]), ex2_fast(sfrag[m][j][3]));
                uint32_t a0 = sPcur + pwr_base + 16 * m * (PSTRIDE * 2) + j * 16;
                asm volatile("st.shared.b32 [%0], %1;" :: "r"(a0), "r"(pb_lo) : "memory");
                asm volatile("st.shared.b32 [%0], %1;" :: "r"(a0 + 8 * (PSTRIDE * 2)), "r"(pb_hi) : "memory");
            }
        }
        // P exchange within wm group (4 warps, 128 threads)
        asm volatile("bar.sync %0, %1;" :: "r"(wm + 1), "r"(128) : "memory");

        // ---- O += P @ V: full 64-key P, this warp's 64 V cols ----
        const uint32_t sVb = sV_u(kt & 1);
        #pragma unroll
        for (int kb2 = 0; kb2 < 4; kb2++) {
            uint32_t a[2][4];
            #pragma unroll
            for (int m = 0; m < 2; m++) {
                ldsm_x4(a[m][0], a[m][1], a[m][2], a[m][3],
                        sPcur + prd_base + 16 * m * (PSTRIDE * 2) + kb2 * 32);
                mma_bf16(acc1[m], a[m][0], a[m][1], a[m][2], a[m][3], ONE2BF, ONE2BF);
            }
            #pragma unroll
            for (int j2 = 0; j2 < 4; j2++) {
                uint32_t b0, b1, b2, b3;
                ldsm_x4_trans(b0, b1, b2, b3,
                              sVb + (kb2 * 16 + vrow4) * (VSTRIDE * 2) + wn * 128 + j2 * 32 + vcolb4);
                #pragma unroll
                for (int m = 0; m < 2; m++) {
                    mma_bf16(acc[m][2 * j2],     a[m][0], a[m][1], a[m][2], a[m][3], b0, b1);
                    mma_bf16(acc[m][2 * j2 + 1], a[m][0], a[m][1], a[m][2], a[m][3], b2, b3);
                }
            }
        }
    }

    // epilogue: normalize + store
    __nv_bfloat16* ob = gatt + ((size_t)b * NTOK + qt * 64) * CC;
    #pragma unroll
    for (int m = 0; m < 2; m++) {
        float inv0 = 1.0f / acc1[m][0];
        float inv1 = 1.0f / acc1[m][2];
        int row0 = 32 * wm + 16 * m + (lane >> 2);
        int colb = wn * 64 + (lane & 3) * 2;
        #pragma unroll
        for (int j = 0; j < 8; j++) {
            int col = colb + j * 8;
            *(uint32_t*)&ob[(size_t)row0 * CC + col]       = pack_bf16(acc[m][j][0] * inv0, acc[m][j][1] * inv0);
            *(uint32_t*)&ob[(size_t)(row0 + 8) * CC + col] = pack_bf16(acc[m][j][2] * inv1, acc[m][j][3] * inv1);
        }
    }
}

// ---------------------------------------------------------------------------
extern "C" void kernel_launch(void* const* d_in, const int* in_sizes, int n_in,
                              void* d_out, int out_size)
{
    const float* x  = (const float*)d_in[0];
    const float* wq = (const float*)d_in[1];
    const float* bq = (const float*)d_in[2];
    const float* wk = (const float*)d_in[3];
    const float* bk = (const float*)d_in[4];
    const float* wv = (const float*)d_in[5];
    const float* bv = (const float*)d_in[6];
    const float* wo = (const float*)d_in[7];
    const float* bo = (const float*)d_in[8];
    float* out = (float*)d_out;

    __nv_bfloat16 *xb, *q, *k, *v, *att, *wqkb, *wvb, *wob;
    float* bqk;
    cudaGetSymbolAddress((void**)&xb,   g_xb);
    cudaGetSymbolAddress((void**)&q,    g_q);
    cudaGetSymbolAddress((void**)&k,    g_k);
    cudaGetSymbolAddress((void**)&v,    g_v);
    cudaGetSymbolAddress((void**)&att,  g_att);
    cudaGetSymbolAddress((void**)&wqkb, g_wqkb);
    cudaGetSymbolAddress((void**)&wvb,  g_wvb);
    cudaGetSymbolAddress((void**)&wob,  g_wob);
    cudaGetSymbolAddress((void**)&bqk,  g_bqk);

    dim3 blk(256);
    const float qscale = 1.4426950408889634f / 5.656854249492380f;  // log2(e)/sqrt(32)

    convert_all_kernel<<<MM * CC / 4 / 256, blk>>>((const float4*)x, wq, bq, wk, bk, wv, wo, qscale);

    const int smem64  = 4 * GEMM_A_STAGE + 4 * 32 * (64 + 8) * 2;    // 59392
    const int smem128 = 4 * GEMM_A_STAGE + 4 * 32 * (128 + 8) * 2;   // 75776
    cudaFuncSetAttribute(tc_gemm_kernel<64, 2>,  cudaFuncAttributeMaxDynamicSharedMemorySize, smem64);
    cudaFuncSetAttribute(tc_gemm_kernel<128, 0>, cudaFuncAttributeMaxDynamicSharedMemorySize, smem128);
    cudaFuncSetAttribute(tc_gemm_kernel<128, 1>, cudaFuncAttributeMaxDynamicSharedMemorySize, smem128);

    // fused Q|K projection, then V projection
    tc_gemm_kernel<64, 2><<<dim3(1, MM / 128), blk, smem64>>>(xb, wqkb, bqk, nullptr, q, k, 64);
    tc_gemm_kernel<128, 0><<<dim3(2, MM / 128), blk, smem128>>>(xb, wvb, bv, nullptr, v, nullptr, CC);

    // attention (64-query CTAs, 2 CTAs/SM for cross-CTA overlap)
    cudaFuncSetAttribute(attn_kernel, cudaFuncAttributeMaxDynamicSharedMemorySize, AT_TOT);
    attn_kernel<<<dim3(NTOK / 64, BB), blk, AT_TOT>>>(q, k, v, att);

    // output projection + bias + residual
    tc_gemm_kernel<128, 1><<<dim3(2, MM / 128), blk, smem128>>>(att, wob, bo, x, out, nullptr, CC);
}